// round 12
// baseline (speedup 1.0000x reference)
#include <cuda_runtime.h>

#define T_STEPS 2048
#define BATCH   256
#define HID     128
#define NTHREADS 512
#define GHS     400      // per-batch ghs stride: 384 rows + 2x8 xpart (parity) 
#define HSW     160      // swizzled h stride per batch: 8 slices * 20 floats

typedef unsigned long long u64;

__device__ __forceinline__ u64 ffma2(u64 a, u64 b, u64 c) {
    u64 d;
    asm("fma.rn.f32x2 %0, %1, %2, %3;" : "=l"(d) : "l"(a), "l"(b), "l"(c));
    return d;
}
__device__ __forceinline__ float hsum2(u64 v) {
    float x, y;
    asm("mov.b64 {%0, %1}, %2;" : "=f"(x), "=f"(y) : "l"(v));
    return x + y;
}

__global__ void __launch_bounds__(NTHREADS, 1)
gru_impute_kernel(const float* __restrict__ x,     // [B, T] (I=1)
                  const float* __restrict__ Wih,   // [384, 1]
                  const float* __restrict__ Whh,   // [384, 128]
                  const float* __restrict__ bih,   // [384]
                  const float* __restrict__ bhh,   // [384]
                  const float* __restrict__ Wfc,   // [1, 128]
                  const float* __restrict__ bfc,   // [1]
                  float* __restrict__ out)
{
    extern __shared__ float sm[];
    float* hsw = sm;                 // 2 * HSW swizzled hidden state (16B aligned)
    float* ghs = sm + 2 * HSW;       // 2 * GHS: raw gate dots [0,384) + xpart[384,400)

    const int tid  = threadIdx.x;
    const int lane = tid & 31;
    const int wrp  = tid >> 5;       // 0..15
    const int ks   = lane & 7;       // k-slice 0..7 (16 k's each)
    const int g    = lane >> 3;      // row-in-group 0..3
    const int b0   = blockIdx.x * 2;

    // ---- one-time staging: 6 rows x 16-k slice per lane into registers ----
    u64 wr[6][8];
    #pragma unroll
    for (int j = 0; j < 6; ++j) {
        const u64* p = reinterpret_cast<const u64*>(Whh + (wrp * 24 + j * 4 + g) * HID + ks * 16);
        #pragma unroll
        for (int i = 0; i < 8; ++i) wr[j][i] = __ldg(p + i);
    }
    for (int idx = tid; idx < 2 * HSW; idx += NTHREADS) hsw[idx] = 0.0f;
    if (tid < 16) { ghs[384 + tid] = 0.0f; ghs[GHS + 384 + tid] = 0.0f; }

    // ---- B-phase constants: all 16 warps, lanes 0..15 (16 units each) ----
    const int bb = wrp >> 3;                    // batch handled in B
    const int ub = ((wrp & 7) << 4) | lane;     // unit 0..127 (valid for lane<16)
    float wih_r = 0.f, wih_z = 0.f, wih_n = 0.f, br = 0.f, bz = 0.f, bnI = 0.f, bhn = 0.f;
    float wfc = 0.f, bf = 0.f, xn = 0.f;
    if (lane < 16) {
        wih_r = Wih[ub];        br  = bih[ub]       + bhh[ub];
        wih_z = Wih[ub + 128];  bz  = bih[ub + 128] + bhh[ub + 128];
        wih_n = Wih[ub + 256];  bnI = bih[ub + 256];
        bhn   = bhh[ub + 256];
        wfc   = Wfc[ub];
        bf    = bfc[0];
        xn    = __ldg(x + (size_t)(b0 + bb) * T_STEPS);
    }
    __syncthreads();

    const ulonglong2* hb0 = reinterpret_cast<const ulonglong2*>(hsw + ks * 20);
    const ulonglong2* hb1 = reinterpret_cast<const ulonglong2*>(hsw + HSW + ks * 20);
    float* st0 = ghs + wrp * 24 + g;            // + j*4 per dot (batch 0)
    float* st1 = st0 + GHS;                     // batch 1

    float* newin = out;                          // [T, B]
    float* pred  = out + T_STEPS * BATCH;        // [B, T-1]

    for (int t = 0; t < T_STEPS; ++t) {
        // ================= Phase A: raw matvec, all 16 warps =================
        {   // batch 0
            u64 q[6] = {0ull, 0ull, 0ull, 0ull, 0ull, 0ull};
            #pragma unroll
            for (int c = 0; c < 4; ++c) {
                ulonglong2 hv = hb0[c];
                #pragma unroll
                for (int j = 0; j < 6; ++j) {
                    q[j] = ffma2(wr[j][2 * c],     hv.x, q[j]);
                    q[j] = ffma2(wr[j][2 * c + 1], hv.y, q[j]);
                }
            }
            float f[6];
            #pragma unroll
            for (int j = 0; j < 6; ++j) f[j] = hsum2(q[j]);
            #pragma unroll
            for (int j = 0; j < 6; ++j) {
                f[j] += __shfl_xor_sync(0xffffffffu, f[j], 1);
                f[j] += __shfl_xor_sync(0xffffffffu, f[j], 2);
                f[j] += __shfl_xor_sync(0xffffffffu, f[j], 4);
            }
            if (ks == 0) {
                #pragma unroll
                for (int j = 0; j < 6; ++j) st0[j * 4] = f[j];
            }
        }
        {   // batch 1
            u64 q[6] = {0ull, 0ull, 0ull, 0ull, 0ull, 0ull};
            #pragma unroll
            for (int c = 0; c < 4; ++c) {
                ulonglong2 hv = hb1[c];
                #pragma unroll
                for (int j = 0; j < 6; ++j) {
                    q[j] = ffma2(wr[j][2 * c],     hv.x, q[j]);
                    q[j] = ffma2(wr[j][2 * c + 1], hv.y, q[j]);
                }
            }
            float f[6];
            #pragma unroll
            for (int j = 0; j < 6; ++j) f[j] = hsum2(q[j]);
            #pragma unroll
            for (int j = 0; j < 6; ++j) {
                f[j] += __shfl_xor_sync(0xffffffffu, f[j], 1);
                f[j] += __shfl_xor_sync(0xffffffffu, f[j], 2);
                f[j] += __shfl_xor_sync(0xffffffffu, f[j], 4);
            }
            if (ks == 0) {
                #pragma unroll
                for (int j = 0; j < 6; ++j) st1[j * 4] = f[j];
            }
        }
        __syncthreads();

        // ================= Phase B: all 16 warps, lanes 0..15 =================
        if (lane < 16) {
            const float* gh = ghs + bb * GHS;
            const float* xp = gh + 384 + (((t & 1) ^ 1) << 3);   // partials from B(t-1)
            float4 xa = *reinterpret_cast<const float4*>(xp);
            float4 xc = *reinterpret_cast<const float4*>(xp + 4);
            float xh = ((xa.x + xa.y) + (xa.z + xa.w))
                     + ((xc.x + xc.y) + (xc.z + xc.w)) + bf;

            float xt = xn;
            if (t + 1 < T_STEPS)
                xn = __ldg(x + (size_t)(b0 + bb) * T_STEPS + t + 1);

            float cur = (t == 0) ? xt : ((xt == 128.0f) ? xh : xt);

            float gr  = fmaf(cur, wih_r, br) + gh[ub];
            float gz  = fmaf(cur, wih_z, bz) + gh[ub + 128];
            float gni = fmaf(cur, wih_n, bnI);

            float r  = __fdividef(1.0f, 1.0f + __expf(-gr));
            float z  = __fdividef(1.0f, 1.0f + __expf(-gz));
            float na = fmaf(r, gh[ub + 256] + bhn, gni);
            float e2 = __expf(2.0f * na);
            float n  = 1.0f - __fdividef(2.0f, e2 + 1.0f);      // tanh

            const int hidx = bb * HSW + (ub >> 4) * 20 + (ub & 15);
            float hold = hsw[hidx];
            float hnew = fmaf(z, hold - n, n);
            hsw[hidx] = hnew;

            if (ub == 0) {
                newin[t * BATCH + b0 + bb] = cur;
                if (t > 0) pred[(size_t)(b0 + bb) * (T_STEPS - 1) + (t - 1)] = xh;
            }
            // x_hat partial for step t+1 (parity buffer t&1)
            float p = hnew * wfc;
            p += __shfl_xor_sync(0x0000ffffu, p, 8);
            p += __shfl_xor_sync(0x0000ffffu, p, 4);
            p += __shfl_xor_sync(0x0000ffffu, p, 2);
            p += __shfl_xor_sync(0x0000ffffu, p, 1);
            if (lane == 0) ghs[bb * GHS + 384 + ((t & 1) << 3) + (wrp & 7)] = p;
        }
        __syncthreads();
    }
}

extern "C" void kernel_launch(void* const* d_in, const int* in_sizes, int n_in,
                              void* d_out, int out_size)
{
    (void)in_sizes; (void)n_in; (void)out_size;
    const float* x    = (const float*)d_in[0];
    const float* Wih  = (const float*)d_in[1];
    const float* Whh  = (const float*)d_in[2];
    const float* bih  = (const float*)d_in[3];
    const float* bhh  = (const float*)d_in[4];
    const float* Wfc  = (const float*)d_in[5];
    const float* bfc  = (const float*)d_in[6];
    float* out = (float*)d_out;

    const size_t smem = (size_t)(2 * HSW + 2 * GHS) * sizeof(float);
    cudaFuncSetAttribute(gru_impute_kernel, cudaFuncAttributeMaxDynamicSharedMemorySize, (int)smem);

    gru_impute_kernel<<<BATCH / 2, NTHREADS, smem>>>(x, Wih, Whh, bih, bhh, Wfc, bfc, out);
}

// round 13
// speedup vs baseline: 1.1145x; 1.1145x over previous
#include <cuda_runtime.h>

#define T_STEPS 2048
#define BATCH   256
#define HID     128
#define NTHREADS 512
#define GHS     400      // per-batch ghs stride: 384 gate rows + 16 xpart (2 parity x 8)
#define HSW     144      // swizzled h stride per batch (128 + 4 pads)

typedef unsigned long long u64;

__device__ __forceinline__ u64 ffma2(u64 a, u64 b, u64 c) {
    u64 d;
    asm("fma.rn.f32x2 %0, %1, %2, %3;" : "=l"(d) : "l"(a), "l"(b), "l"(c));
    return d;
}
__device__ __forceinline__ float hsum2(u64 v) {
    float x, y;
    asm("mov.b64 {%0, %1}, %2;" : "=f"(x), "=f"(y) : "l"(v));
    return x + y;
}

__global__ void __launch_bounds__(NTHREADS, 1)
gru_impute_kernel(const float* __restrict__ x,     // [B, T] (I=1)
                  const float* __restrict__ Wih,   // [384, 1]
                  const float* __restrict__ Whh,   // [384, 128]
                  const float* __restrict__ bih,   // [384]
                  const float* __restrict__ bhh,   // [384]
                  const float* __restrict__ Wfc,   // [1, 128]
                  const float* __restrict__ bfc,   // [1]
                  float* __restrict__ out)
{
    extern __shared__ float sm[];
    float* hsw = sm;                 // 2 * HSW swizzled hidden state (16B aligned)
    float* ghs = sm + 2 * HSW;       // 2 * GHS: gate pre-acts [0,384) + xpart [384,400)

    const int tid  = threadIdx.x;
    const int lane = tid & 31;
    const int wrp  = tid >> 5;       // 0..15
    const int ks   = lane & 3;       // k-slice 0..3 (32 k's each)
    const int g    = lane >> 2;      // row-in-group 0..7
    const int b0   = blockIdx.x * 2;
    const int r0   = wrp * 24 + g;

    // ---- one-time staging: Whh slices into registers (champion layout) ----
    u64 wr0[16], wr1[16], wr2[16];
    float bh0, bh1, bh2;
    {
        const u64* p0 = reinterpret_cast<const u64*>(Whh + (r0     ) * HID + ks * 32);
        const u64* p1 = reinterpret_cast<const u64*>(Whh + (r0 +  8) * HID + ks * 32);
        const u64* p2 = reinterpret_cast<const u64*>(Whh + (r0 + 16) * HID + ks * 32);
        #pragma unroll
        for (int i = 0; i < 16; ++i) { wr0[i] = __ldg(p0 + i); wr1[i] = __ldg(p1 + i); wr2[i] = __ldg(p2 + i); }
        bh0 = bhh[r0]; bh1 = bhh[r0 + 8]; bh2 = bhh[r0 + 16];
    }
    for (int idx = tid; idx < 2 * HSW; idx += NTHREADS) hsw[idx] = 0.0f;
    if (tid < 16) { ghs[384 + tid] = 0.0f; ghs[GHS + 384 + tid] = 0.0f; }

    // ---- B-phase constants: all 16 warps, lanes 0..15 (16 units each) ----
    const int bb = wrp >> 3;                    // batch handled in B
    const int ub = ((wrp & 7) << 4) | (lane & 15);  // unit 0..127
    float wih_r = 0.f, wih_z = 0.f, wih_n = 0.f, bih_r = 0.f, bih_z = 0.f, bih_n = 0.f;
    float wfc = 0.f, bf = 0.f, xn = 0.f;
    if (lane < 16) {
        wih_r = Wih[ub];        bih_r = bih[ub];
        wih_z = Wih[ub + 128];  bih_z = bih[ub + 128];
        wih_n = Wih[ub + 256];  bih_n = bih[ub + 256];
        wfc   = Wfc[ub];
        bf    = bfc[0];
        xn    = __ldg(x + (size_t)(b0 + bb) * T_STEPS);
    }
    __syncthreads();

    const ulonglong2* hb0 = reinterpret_cast<const ulonglong2*>(hsw + ks * 36);
    const ulonglong2* hb1 = reinterpret_cast<const ulonglong2*>(hsw + HSW + ks * 36);

    float* newin = out;                          // [T, B]
    float* pred  = out + T_STEPS * BATCH;        // [B, T-1]

    for (int t = 0; t < T_STEPS; ++t) {
        // ================= Phase A: matvec, all 16 warps (champion R7) =================
        {
            u64 a00 = 0ull, a01 = 0ull, a02 = 0ull;
            u64 a10 = 0ull, a11 = 0ull, a12 = 0ull;
            #pragma unroll
            for (int c = 0; c < 8; ++c) {
                ulonglong2 hv = hb0[c];
                a00 = ffma2(wr0[2 * c],     hv.x, a00);
                a01 = ffma2(wr1[2 * c],     hv.x, a01);
                a02 = ffma2(wr2[2 * c],     hv.x, a02);
                a00 = ffma2(wr0[2 * c + 1], hv.y, a00);
                a01 = ffma2(wr1[2 * c + 1], hv.y, a01);
                a02 = ffma2(wr2[2 * c + 1], hv.y, a02);
            }
            #pragma unroll
            for (int c = 0; c < 8; ++c) {
                ulonglong2 hv = hb1[c];
                a10 = ffma2(wr0[2 * c],     hv.x, a10);
                a11 = ffma2(wr1[2 * c],     hv.x, a11);
                a12 = ffma2(wr2[2 * c],     hv.x, a12);
                a10 = ffma2(wr0[2 * c + 1], hv.y, a10);
                a11 = ffma2(wr1[2 * c + 1], hv.y, a11);
                a12 = ffma2(wr2[2 * c + 1], hv.y, a12);
            }
            float f0 = hsum2(a00), f1 = hsum2(a01), f2 = hsum2(a02);
            float f3 = hsum2(a10), f4 = hsum2(a11), f5 = hsum2(a12);
            f0 += __shfl_xor_sync(0xffffffffu, f0, 1); f0 += __shfl_xor_sync(0xffffffffu, f0, 2);
            f1 += __shfl_xor_sync(0xffffffffu, f1, 1); f1 += __shfl_xor_sync(0xffffffffu, f1, 2);
            f2 += __shfl_xor_sync(0xffffffffu, f2, 1); f2 += __shfl_xor_sync(0xffffffffu, f2, 2);
            f3 += __shfl_xor_sync(0xffffffffu, f3, 1); f3 += __shfl_xor_sync(0xffffffffu, f3, 2);
            f4 += __shfl_xor_sync(0xffffffffu, f4, 1); f4 += __shfl_xor_sync(0xffffffffu, f4, 2);
            f5 += __shfl_xor_sync(0xffffffffu, f5, 1); f5 += __shfl_xor_sync(0xffffffffu, f5, 2);
            if (ks == 0) {
                ghs[r0]            = f0 + bh0;
                ghs[r0 + 8]        = f1 + bh1;
                ghs[r0 + 16]       = f2 + bh2;
                ghs[GHS + r0]      = f3 + bh0;
                ghs[GHS + r0 + 8]  = f4 + bh1;
                ghs[GHS + r0 + 16] = f5 + bh2;
            }
        }
        __syncthreads();

        // ============ Phase B: all 16 warps, lanes 0..15 (R12-validated layout) ============
        if (lane < 16) {
            const float* gh = ghs + bb * GHS;
            const float* xp = gh + 384 + (((t & 1) ^ 1) << 3);   // partials written at t-1
            float4 xa = *reinterpret_cast<const float4*>(xp);
            float4 xc = *reinterpret_cast<const float4*>(xp + 4);
            float xh = ((xa.x + xa.y) + (xa.z + xa.w))
                     + ((xc.x + xc.y) + (xc.z + xc.w)) + bf;

            float xt = xn;
            if (t + 1 < T_STEPS)
                xn = __ldg(x + (size_t)(b0 + bb) * T_STEPS + t + 1);

            float cur = (t == 0) ? xt : ((xt == 128.0f) ? xh : xt);

            float gr  = fmaf(cur, wih_r, bih_r) + gh[ub];
            float gz  = fmaf(cur, wih_z, bih_z) + gh[ub + 128];
            float gni = fmaf(cur, wih_n, bih_n);

            float r  = __fdividef(1.0f, 1.0f + __expf(-gr));
            float z  = __fdividef(1.0f, 1.0f + __expf(-gz));
            float na = fmaf(r, gh[ub + 256], gni);      // bhh_n already in gh (A adds it)
            float e2 = __expf(2.0f * na);
            float n  = 1.0f - __fdividef(2.0f, e2 + 1.0f);   // tanh

            const int hidx = bb * HSW + ub + (ub >> 5) * 4;  // champion swizzle
            float hold = hsw[hidx];
            float hnew = fmaf(z, hold - n, n);
            hsw[hidx] = hnew;

            if (ub == 0) {
                newin[t * BATCH + b0 + bb] = cur;
                if (t > 0) pred[(size_t)(b0 + bb) * (T_STEPS - 1) + (t - 1)] = xh;
            }
            // x_hat partial for step t+1 (parity buffer t&1)
            float p = hnew * wfc;
            p += __shfl_xor_sync(0x0000ffffu, p, 8);
            p += __shfl_xor_sync(0x0000ffffu, p, 4);
            p += __shfl_xor_sync(0x0000ffffu, p, 2);
            p += __shfl_xor_sync(0x0000ffffu, p, 1);
            if ((lane & 15) == 0) ghs[bb * GHS + 384 + ((t & 1) << 3) + (wrp & 7)] = p;
        }
        __syncthreads();
    }
}

extern "C" void kernel_launch(void* const* d_in, const int* in_sizes, int n_in,
                              void* d_out, int out_size)
{
    (void)in_sizes; (void)n_in; (void)out_size;
    const float* x    = (const float*)d_in[0];
    const float* Wih  = (const float*)d_in[1];
    const float* Whh  = (const float*)d_in[2];
    const float* bih  = (const float*)d_in[3];
    const float* bhh  = (const float*)d_in[4];
    const float* Wfc  = (const float*)d_in[5];
    const float* bfc  = (const float*)d_in[6];
    float* out = (float*)d_out;

    const size_t smem = (size_t)(2 * HSW + 2 * GHS) * sizeof(float);
    cudaFuncSetAttribute(gru_impute_kernel, cudaFuncAttributeMaxDynamicSharedMemorySize, (int)smem);

    gru_impute_kernel<<<BATCH / 2, NTHREADS, smem>>>(x, Wih, Whh, bih, bhh, Wfc, bfc, out);
}

// round 14
// speedup vs baseline: 1.3861x; 1.2437x over previous
#include <cuda_runtime.h>

#define T_STEPS 2048
#define BATCH   256
#define HID     128
#define NTHREADS 512
#define HSW     144      // swizzled h stride per batch (128 + 4 pads)
#define GHS4    1544     // per-batch: 1536 raw ks-partials + 8 xpart (2 parity x 4)

typedef unsigned long long u64;

__device__ __forceinline__ u64 ffma2(u64 a, u64 b, u64 c) {
    u64 d;
    asm("fma.rn.f32x2 %0, %1, %2, %3;" : "=l"(d) : "l"(a), "l"(b), "l"(c));
    return d;
}
__device__ __forceinline__ float hsum2(u64 v) {
    float x, y;
    asm("mov.b64 {%0, %1}, %2;" : "=f"(x), "=f"(y) : "l"(v));
    return x + y;
}

__global__ void __launch_bounds__(NTHREADS, 1)
gru_impute_kernel(const float* __restrict__ x,     // [B, T] (I=1)
                  const float* __restrict__ Wih,   // [384, 1]
                  const float* __restrict__ Whh,   // [384, 128]
                  const float* __restrict__ bih,   // [384]
                  const float* __restrict__ bhh,   // [384]
                  const float* __restrict__ Wfc,   // [1, 128]
                  const float* __restrict__ bfc,   // [1]
                  float* __restrict__ out)
{
    extern __shared__ float sm[];
    float* hsw = sm;                 // 2 * HSW swizzled hidden state (16B aligned)
    float* ghs = sm + 2 * HSW;       // 2 * GHS4: raw partials [0,1536) + xpart [1536,1544)

    const int tid  = threadIdx.x;
    const int lane = tid & 31;
    const int wrp  = tid >> 5;       // 0..15
    const int ks   = lane & 3;       // k-slice 0..3 (32 k's each)
    const int b0   = blockIdx.x * 2;
    const int r0   = wrp * 24 + (lane >> 2);

    // ---- one-time staging: Whh slices into registers (raw; ALL bias in B) ----
    u64 wr0[16], wr1[16], wr2[16];
    {
        const u64* p0 = reinterpret_cast<const u64*>(Whh + (r0     ) * HID + ks * 32);
        const u64* p1 = reinterpret_cast<const u64*>(Whh + (r0 +  8) * HID + ks * 32);
        const u64* p2 = reinterpret_cast<const u64*>(Whh + (r0 + 16) * HID + ks * 32);
        #pragma unroll
        for (int i = 0; i < 16; ++i) { wr0[i] = __ldg(p0 + i); wr1[i] = __ldg(p1 + i); wr2[i] = __ldg(p2 + i); }
    }
    for (int idx = tid; idx < 2 * HSW; idx += NTHREADS) hsw[idx] = 0.0f;
    if (tid < 8) { ghs[1536 + tid] = 0.0f; ghs[GHS4 + 1536 + tid] = 0.0f; }

    // ---- B-phase per-thread constants (threads 0..255 = warps 0-7) ----
    const int ub = tid & 127;
    const int b  = tid >> 7;
    float wih_r = 0.f, wih_z = 0.f, wih_n = 0.f, br = 0.f, bz = 0.f, bnI = 0.f, bhn = 0.f;
    float wfc = 0.f, bf = 0.f, xn = 0.f;
    if (tid < 256) {
        wih_r = Wih[ub];        br  = bih[ub]       + bhh[ub];
        wih_z = Wih[ub + 128];  bz  = bih[ub + 128] + bhh[ub + 128];
        wih_n = Wih[ub + 256];  bnI = bih[ub + 256];
        bhn   = bhh[ub + 256];
        wfc   = Wfc[ub];
        bf    = bfc[0];
        xn    = __ldg(x + (size_t)(b0 + b) * T_STEPS);
    }
    __syncthreads();

    const ulonglong2* hb0 = reinterpret_cast<const ulonglong2*>(hsw + ks * 36);
    const ulonglong2* hb1 = reinterpret_cast<const ulonglong2*>(hsw + HSW + ks * 36);
    float* pa0 = ghs + wrp * 96 + lane;     // raw partial slot: row*4+ks; +32 per row-group
    float* pa1 = pa0 + GHS4;

    float* newin = out;                      // [T, B]
    float* pred  = out + T_STEPS * BATCH;    // [B, T-1]

    for (int t = 0; t < T_STEPS; ++t) {
        // ========== Phase A: matvec, all 16 warps; raw partials, NO shuffles ==========
        {
            u64 a00 = 0ull, a01 = 0ull, a02 = 0ull;
            u64 a10 = 0ull, a11 = 0ull, a12 = 0ull;
            #pragma unroll
            for (int c = 0; c < 8; ++c) {
                ulonglong2 hv = hb0[c];
                a00 = ffma2(wr0[2 * c],     hv.x, a00);
                a01 = ffma2(wr1[2 * c],     hv.x, a01);
                a02 = ffma2(wr2[2 * c],     hv.x, a02);
                a00 = ffma2(wr0[2 * c + 1], hv.y, a00);
                a01 = ffma2(wr1[2 * c + 1], hv.y, a01);
                a02 = ffma2(wr2[2 * c + 1], hv.y, a02);
            }
            #pragma unroll
            for (int c = 0; c < 8; ++c) {
                ulonglong2 hv = hb1[c];
                a10 = ffma2(wr0[2 * c],     hv.x, a10);
                a11 = ffma2(wr1[2 * c],     hv.x, a11);
                a12 = ffma2(wr2[2 * c],     hv.x, a12);
                a10 = ffma2(wr0[2 * c + 1], hv.y, a10);
                a11 = ffma2(wr1[2 * c + 1], hv.y, a11);
                a12 = ffma2(wr2[2 * c + 1], hv.y, a12);
            }
            pa0[0]  = hsum2(a00);            // row r0,    slice ks  (batch 0)
            pa0[32] = hsum2(a01);            // row r0+8
            pa0[64] = hsum2(a02);            // row r0+16
            pa1[0]  = hsum2(a10);            // batch 1
            pa1[32] = hsum2(a11);
            pa1[64] = hsum2(a12);
        }
        __syncthreads();

        // ========== Phase B: gates + update, threads 0..255 (float4 gathers) ==========
        if (tid < 256) {
            const float* g4 = ghs + b * GHS4;
            // x_hat partials written at step t-1 into parity buffer (t-1)&1
            const float* xp = g4 + 1536 + (((t & 1) ^ 1) << 2);
            float4 xq = *reinterpret_cast<const float4*>(xp);
            float xh = (xq.x + xq.y) + (xq.z + xq.w) + bf;

            float4 pr = *reinterpret_cast<const float4*>(g4 + 4 * ub);
            float4 pz = *reinterpret_cast<const float4*>(g4 + 512 + 4 * ub);
            float4 pn = *reinterpret_cast<const float4*>(g4 + 1024 + 4 * ub);

            float xt = xn;
            if (t + 1 < T_STEPS)
                xn = __ldg(x + (size_t)(b0 + b) * T_STEPS + t + 1);

            float cur = (t == 0) ? xt : ((xt == 128.0f) ? xh : xt);

            float sr = (pr.x + pr.y) + (pr.z + pr.w);
            float sz = (pz.x + pz.y) + (pz.z + pz.w);
            float sn = (pn.x + pn.y) + (pn.z + pn.w);

            float gr  = fmaf(cur, wih_r, br) + sr;
            float gz  = fmaf(cur, wih_z, bz) + sz;
            float gni = fmaf(cur, wih_n, bnI);

            float r  = __fdividef(1.0f, 1.0f + __expf(-gr));
            float z  = __fdividef(1.0f, 1.0f + __expf(-gz));
            float na = fmaf(r, sn + bhn, gni);
            float e2 = __expf(2.0f * na);
            float n  = 1.0f - __fdividef(2.0f, e2 + 1.0f);   // tanh

            const int hidx = b * HSW + ub + (ub >> 5) * 4;   // champion swizzle
            float hold = hsw[hidx];
            float hnew = fmaf(z, hold - n, n);
            hsw[hidx] = hnew;

            if (ub == 0) {
                newin[t * BATCH + b0 + b] = cur;
                if (t > 0) pred[(size_t)(b0 + b) * (T_STEPS - 1) + (t - 1)] = xh;
            }
            // x_hat partial for step t+1 -> parity buffer t&1 (no same-phase race)
            float p = hnew * wfc;
            #pragma unroll
            for (int off = 16; off >= 1; off >>= 1)
                p += __shfl_xor_sync(0xffffffffu, p, off);
            if (lane == 0) ghs[b * GHS4 + 1536 + ((t & 1) << 2) + (wrp & 3)] = p;
        }
        __syncthreads();
    }
}

extern "C" void kernel_launch(void* const* d_in, const int* in_sizes, int n_in,
                              void* d_out, int out_size)
{
    (void)in_sizes; (void)n_in; (void)out_size;
    const float* x    = (const float*)d_in[0];
    const float* Wih  = (const float*)d_in[1];
    const float* Whh  = (const float*)d_in[2];
    const float* bih  = (const float*)d_in[3];
    const float* bhh  = (const float*)d_in[4];
    const float* Wfc  = (const float*)d_in[5];
    const float* bfc  = (const float*)d_in[6];
    float* out = (float*)d_out;

    const size_t smem = (size_t)(2 * HSW + 2 * GHS4) * sizeof(float);
    cudaFuncSetAttribute(gru_impute_kernel, cudaFuncAttributeMaxDynamicSharedMemorySize, (int)smem);

    gru_impute_kernel<<<BATCH / 2, NTHREADS, smem>>>(x, Wih, Whh, bih, bhh, Wfc, bfc, out);
}